// round 1
// baseline (speedup 1.0000x reference)
#include <cuda_runtime.h>
#include <math.h>

#define EPSF 1e-12f

struct V3 { float x, y, z; };

static __device__ __forceinline__ V3 v3sub(V3 a, V3 b) { return {a.x - b.x, a.y - b.y, a.z - b.z}; }
static __device__ __forceinline__ V3 v3cross(V3 a, V3 b) {
    return {a.y * b.z - a.z * b.y,
            a.z * b.x - a.x * b.z,
            a.x * b.y - a.y * b.x};
}
static __device__ __forceinline__ float v3dot(V3 a, V3 b) { return a.x * b.x + a.y * b.y + a.z * b.z; }

static __device__ __forceinline__ float smooth_clamp(float x, float lb, float rb,
                                                     float slope_l, float slope_r) {
    float t = (x - lb) / (rb - lb);
    float z = 4.0f * t - 2.0f;
    // sigmoid(z) = 1/(1+exp(-z))
    float sig = 1.0f / (1.0f + expf(-z));
    float core = lb + (rb - lb) * sig;
    float lo = fminf(x - lb, 0.0f);
    float hi = fmaxf(x - rb, 0.0f);
    return core + slope_l * lo + slope_r * hi;
}

__global__ void __launch_bounds__(256) face_gaussian_kernel(
    const float* __restrict__ va,
    const float* __restrict__ vb,
    const float* __restrict__ vc,
    const float* __restrict__ rotz,
    const float* __restrict__ gsx,
    const float* __restrict__ gsy,
    const float* __restrict__ gsz,
    const float* __restrict__ color,
    const float* __restrict__ logop,
    float* __restrict__ out,
    int F)
{
    int i = blockIdx.x * blockDim.x + threadIdx.x;
    if (i >= F) return;

    const int i3 = 3 * i;
    V3 a = {va[i3], va[i3 + 1], va[i3 + 2]};
    V3 b = {vb[i3], vb[i3 + 1], vb[i3 + 2]};
    V3 c = {vc[i3], vc[i3 + 1], vc[i3 + 2]};

    V3 e1 = v3sub(b, a);
    V3 e2 = v3sub(c, a);
    V3 n = v3cross(e1, e2);
    float n_norm = sqrtf(v3dot(n, n));
    float area = 0.5f * n_norm;

    float inv_e1 = 1.0f / (sqrtf(v3dot(e1, e1)) + EPSF);
    V3 ax = {e1.x * inv_e1, e1.y * inv_e1, e1.z * inv_e1};
    float inv_n = 1.0f / (n_norm + EPSF);
    V3 az = {n.x * inv_n, n.y * inv_n, n.z * inv_n};
    V3 ay = v3cross(az, ax);

    // centroid
    float tx = (a.x + b.x + c.x) * (1.0f / 3.0f);
    float ty = (a.y + b.y + c.y) * (1.0f / 3.0f);
    float tz = (a.z + b.z + c.z) * (1.0f / 3.0f);

    // rotation matrix with columns ax, ay, az
    float m00 = ax.x, m01 = ay.x, m02 = az.x;
    float m10 = ax.y, m11 = ay.y, m12 = az.y;
    float m20 = ax.z, m21 = ay.z, m22 = az.z;

    float tr = m00 + m11 + m22;

    // argmax of [tr, m00, m11, m22], first-index-wins tie rule
    int idx = 0;
    float best = tr;
    if (m00 > best) { best = m00; idx = 1; }
    if (m11 > best) { best = m11; idx = 2; }
    if (m22 > best) { best = m22; idx = 3; }

    float qw, qx, qy, qz;
    if (idx == 0) {
        float t0 = fmaxf(1.0f + tr, 1e-8f);
        float s0 = 0.5f / sqrtf(t0);
        qw = t0 * s0;
        qx = (m21 - m12) * s0;
        qy = (m02 - m20) * s0;
        qz = (m10 - m01) * s0;
    } else if (idx == 1) {
        float t1 = fmaxf(1.0f + m00 - m11 - m22, 1e-8f);
        float s1 = 0.5f / sqrtf(t1);
        qw = (m21 - m12) * s1;
        qx = t1 * s1;
        qy = (m01 + m10) * s1;
        qz = (m02 + m20) * s1;
    } else if (idx == 2) {
        float t2 = fmaxf(1.0f - m00 + m11 - m22, 1e-8f);
        float s2 = 0.5f / sqrtf(t2);
        qw = (m02 - m20) * s2;
        qx = (m01 + m10) * s2;
        qy = t2 * s2;
        qz = (m12 + m21) * s2;
    } else {
        float t3 = fmaxf(1.0f - m00 - m11 + m22, 1e-8f);
        float s3 = 0.5f / sqrtf(t3);
        qw = (m10 - m01) * s3;
        qx = (m02 + m20) * s3;
        qy = (m12 + m21) * s3;
        qz = t3 * s3;
    }

    // multiply by local z-rotation quat (cos h, 0, 0, sin h)
    float half = rotz[i] * 0.5f;
    float sh, ch;
    sincosf(half, &sh, &ch);
    float wqw = qw * ch - qz * sh;
    float wqx = qx * ch + qy * sh;
    float wqy = qy * ch - qx * sh;
    float wqz = qw * sh + qz * ch;

    // scales
    float sf = sqrtf(area);
    float sx = sf * smooth_clamp(expf(gsx[i]), 0.1f, 3.0f, 0.0f, 0.005f);
    float sy = sf * smooth_clamp(expf(gsy[i]), 0.1f, 3.0f, 0.0f, 0.005f);
    float sz = smooth_clamp(sf * expf(gsz[i]), 0.001f, 0.01f, 0.0f, 0.005f);

    float col0 = color[i3];
    float col1 = color[i3 + 1];
    float col2 = color[i3 + 2];
    float opacity = expf(logop[i]);

    // Output row: t(3) | quat(4) | scale(3) | color(3) | opacity(1) = 14 floats.
    // Row byte offset = 56*i, divisible by 8 -> float2 stores are legal.
    float2* o2 = reinterpret_cast<float2*>(out + (size_t)i * 14);
    o2[0] = make_float2(tx, ty);
    o2[1] = make_float2(tz, wqw);
    o2[2] = make_float2(wqx, wqy);
    o2[3] = make_float2(wqz, sx);
    o2[4] = make_float2(sy, sz);
    o2[5] = make_float2(col0, col1);
    o2[6] = make_float2(col2, opacity);
}

extern "C" void kernel_launch(void* const* d_in, const int* in_sizes, int n_in,
                              void* d_out, int out_size)
{
    const float* va    = (const float*)d_in[0];
    const float* vb    = (const float*)d_in[1];
    const float* vc    = (const float*)d_in[2];
    const float* rotz  = (const float*)d_in[3];
    const float* gsx   = (const float*)d_in[4];
    const float* gsy   = (const float*)d_in[5];
    const float* gsz   = (const float*)d_in[6];
    const float* color = (const float*)d_in[7];
    const float* logop = (const float*)d_in[8];
    float* out = (float*)d_out;

    int F = in_sizes[3];  // gp_rot_z element count
    int threads = 256;
    int blocks = (F + threads - 1) / threads;
    face_gaussian_kernel<<<blocks, threads>>>(va, vb, vc, rotz, gsx, gsy, gsz,
                                              color, logop, out, F);
}